// round 3
// baseline (speedup 1.0000x reference)
#include <cuda_runtime.h>
#include <stdint.h>

// ============================================================================
// One-sweep speculative radix-select threshold kernel.
//
// thresh = rank-mf (0-based) entry of descending sort of all inputs.
// out[i] = x[i] < thresh ? 0 : x[i].
//
// Key map (order-preserving): key = u ^ (sign ? 0xFFFFFFFF : 0x80000000).
//
// Spec path (expected): pass1 writes out thresholded at 1.75, compacts
// (key, idx) pairs of all candidates >= 1.75 and builds a 64K-bin hist of
// key>>16. If #candidates >= mf+1 (exact device check), true thresh >= 1.75,
// so out is already correct except candidates below the true thresh, which a
// tiny fixup pass zeroes. Otherwise a fully general histogram fallback
// recomputes thresh and rewrites out entirely.
// ============================================================================

#define NB     1024
#define NT     256
#define NWARP  (NB * NT / 32)     // 8192
#define SLICE  512u               // pairs per warp slice (mean ~110, cap 512)
#define FKEY   0xBFE00000u        // key(+1.75f)
#define HBINS  65536

__device__ unsigned g_histA[HBINS];
__device__ unsigned g_histB[HBINS];
__device__ unsigned g_histF[HBINS];
__device__ uint2    g_pair[NWARP * SLICE];   // 32 MB
__device__ unsigned g_warpcnt[NWARP];
__device__ unsigned g_nscratch;
__device__ int      g_mode;      // 0=spec ok, 1=fallback, 2=trivial
__device__ int      g_overflow;
__device__ unsigned g_prefix;    // selected high 16 bits
__device__ unsigned g_rank;      // residual rank
__device__ unsigned g_key32;     // final exact key
__device__ float    g_thresh;

__device__ __forceinline__ unsigned fmap_u(unsigned u) {
    return u ^ ((unsigned)((int)u >> 31) | 0x80000000u);
}
__device__ __forceinline__ float finv_map(unsigned k) {
    unsigned u = (k & 0x80000000u) ? (k ^ 0x80000000u) : ~k;
    return __uint_as_float(u);
}

// ---------------------------------------------------------------------------
__global__ void k_init() {
    int i = blockIdx.x * blockDim.x + threadIdx.x;   // 192 * 1024 = 196608
    if (i < HBINS)              g_histA[i] = 0;
    else if (i < 2 * HBINS)     g_histB[i - HBINS] = 0;
    else                        g_histF[i - 2 * HBINS] = 0;
    if (i == 0) {
        g_nscratch = 0; g_mode = 0; g_overflow = 0;
        g_prefix = 0; g_rank = 0; g_key32 = 0; g_thresh = 0.0f;
    }
}

// ---------------------------------------------------------------------------
// Pass 1: read all, write thresholded-at-1.75 output, compact (key,idx)
// pairs into per-warp slices, 64K-bin hist of key>>16 via spread atomics.
__global__ void __launch_bounds__(NT) k_pass1(
        const uint4* __restrict__ a0, int n0,
        const uint4* __restrict__ a1, int n1,
        const uint4* __restrict__ a2, int n2,
        uint4* __restrict__ out) {
    int tid = blockIdx.x * blockDim.x + threadIdx.x;
    int stride = gridDim.x * blockDim.x;
    unsigned lane = threadIdx.x & 31u;
    unsigned gw = (unsigned)tid >> 5;
    unsigned sbase = gw * SLICE;
    unsigned lt = (lane == 31u) ? 0x7FFFFFFFu : ((1u << lane) - 1u);
    unsigned me = 1u << lane;
    unsigned wo = 0;
    bool ovf = false;

#define P1_BODY(ARR, N, OUTP, EO)                                             \
    for (int i = tid; i < (N); i += stride) {                                 \
        uint4 v = __ldcs(&(ARR)[i]);                                          \
        unsigned k0 = fmap_u(v.x), k1 = fmap_u(v.y);                          \
        unsigned k2 = fmap_u(v.z), k3 = fmap_u(v.w);                          \
        bool c0 = k0 >= FKEY, c1 = k1 >= FKEY;                                \
        bool c2 = k2 >= FKEY, c3 = k3 >= FKEY;                                \
        uint4 w;                                                              \
        w.x = c0 ? v.x : 0u;  w.y = c1 ? v.y : 0u;                            \
        w.z = c2 ? v.z : 0u;  w.w = c3 ? v.w : 0u;                            \
        __stcs(&(OUTP)[i], w);                                                \
        unsigned b0 = __ballot_sync(0xFFFFFFFFu, c0);                         \
        unsigned b1 = __ballot_sync(0xFFFFFFFFu, c1);                         \
        unsigned b2 = __ballot_sync(0xFFFFFFFFu, c2);                         \
        unsigned b3 = __ballot_sync(0xFFFFFFFFu, c3);                         \
        unsigned t0 = __popc(b0), t1 = __popc(b1);                            \
        unsigned t2 = __popc(b2), t3 = __popc(b3);                            \
        unsigned tot = t0 + t1 + t2 + t3;                                     \
        if (tot) {                                                            \
            if (wo + tot <= SLICE) {                                          \
                unsigned o = sbase + wo;                                      \
                unsigned ib = (EO) + 4u * (unsigned)i;                        \
                if (c0) { g_pair[o + __popc(b0 & lt)] = make_uint2(k0, ib);   \
                          atomicAdd(&g_histA[k0 >> 16], 1u); }                \
                o += t0;                                                      \
                if (c1) { g_pair[o + __popc(b1 & lt)] = make_uint2(k1, ib+1); \
                          atomicAdd(&g_histA[k1 >> 16], 1u); }                \
                o += t1;                                                      \
                if (c2) { g_pair[o + __popc(b2 & lt)] = make_uint2(k2, ib+2); \
                          atomicAdd(&g_histA[k2 >> 16], 1u); }                \
                o += t2;                                                      \
                if (c3) { g_pair[o + __popc(b3 & lt)] = make_uint2(k3, ib+3); \
                          atomicAdd(&g_histA[k3 >> 16], 1u); }                \
                wo += tot;                                                    \
            } else {                                                          \
                ovf = true;                                                   \
            }                                                                 \
        }                                                                     \
    }
    P1_BODY(a0, n0, out, 0u)
    P1_BODY(a1, n1, out + n0, 4u * (unsigned)n0)
    P1_BODY(a2, n2, out + n0 + n1, 4u * (unsigned)(n0 + n1))
#undef P1_BODY

    if (ovf) g_overflow = 1;
    if (lane == 0) {
        g_warpcnt[gw] = wo;
        atomicAdd(&g_nscratch, wo);
    }
}

// ---------------------------------------------------------------------------
// Parallel descending rank-select over a 64K-bin hist. Whole 1024-thread block.
__device__ __forceinline__ void block_select64k(const unsigned* hist,
                                                unsigned r_in,
                                                unsigned* out_bin,
                                                unsigned* out_r) {
    __shared__ unsigned tsum[1024];
    __shared__ unsigned wsum[32];
    __shared__ unsigned res[2];
    int tid = threadIdx.x;
    unsigned lane = tid & 31;
    unsigned s = 0;
    int base = tid * 64;
#pragma unroll 8
    for (int j = 0; j < 64; j++) s += hist[base + j];
    tsum[tid] = s;
    unsigned ws = s;
    ws += __shfl_xor_sync(0xFFFFFFFFu, ws, 16);
    ws += __shfl_xor_sync(0xFFFFFFFFu, ws, 8);
    ws += __shfl_xor_sync(0xFFFFFFFFu, ws, 4);
    ws += __shfl_xor_sync(0xFFFFFFFFu, ws, 2);
    ws += __shfl_xor_sync(0xFFFFFFFFu, ws, 1);
    if (lane == 0) wsum[tid >> 5] = ws;
    __syncthreads();
    if (tid == 0) {
        unsigned r = r_in;
        int w = 0;
        for (w = 31; w > 0; w--) { if (r < wsum[w]) break; r -= wsum[w]; }
        int t = 0;
        for (t = 31; t > 0; t--) {
            unsigned c = tsum[w * 32 + t];
            if (r < c) break; r -= c;
        }
        int b = (w * 32 + t) * 64;
        int j = 0;
        for (j = 63; j > 0; j--) { unsigned c = hist[b + j]; if (r < c) break; r -= c; }
        res[0] = (unsigned)(b + j);
        res[1] = r;
    }
    __syncthreads();
    *out_bin = res[0];
    *out_r = res[1];
}

// ---------------------------------------------------------------------------
__global__ void k_selectA(const int* mf_ptr, int host_mf, long long ntot) {
    __shared__ int smode;
    __shared__ unsigned srank;
    if (threadIdx.x == 0) {
        long long mf = (mf_ptr != nullptr) ? (long long)(*mf_ptr)
                                           : (long long)host_mf;
        if (mf < 0) mf = 0;
        int mode;
        if (mf >= ntot)                { mode = 2; g_thresh = 0.0f; }
        else if (g_overflow || (long long)g_nscratch < mf + 1) mode = 1;
        else                             mode = 0;
        g_mode = mode; smode = mode;
        srank = (unsigned)mf;
        g_rank = srank;
    }
    __syncthreads();
    if (smode == 0) {
        unsigned bin, r;
        block_select64k(g_histA, srank, &bin, &r);
        if (threadIdx.x == 0) { g_prefix = bin; g_rank = r; }
    }
}

// ---------------------------------------------------------------------------
// SPEC path: low-16-bit hist over scratch pairs matching prefix.
__global__ void __launch_bounds__(NT) k_histB() {
    if (g_mode != 0) return;
    const unsigned pref = g_prefix;
    unsigned lane = threadIdx.x & 31u;
    unsigned gw = (blockIdx.x * blockDim.x + threadIdx.x) >> 5;
    unsigned nw = (gridDim.x * blockDim.x) >> 5;
    for (unsigned s = gw; s < NWARP; s += nw) {
        unsigned cnt = g_warpcnt[s];
        if (cnt > SLICE) cnt = SLICE;
        const uint2* sp = &g_pair[s * SLICE];
        for (unsigned i = lane; i < cnt; i += 32) {
            uint2 p = sp[i];
            if ((p.x >> 16) == pref)
                atomicAdd(&g_histB[p.x & 0xFFFFu], 1u);
        }
    }
}

// ---------------------------------------------------------------------------
// FALLBACK: full-read 64K-bin hist of key>>16 (no compaction -> no overflow).
__global__ void __launch_bounds__(NT) k_fb_histA(
        const uint4* __restrict__ a0, int n0,
        const uint4* __restrict__ a1, int n1,
        const uint4* __restrict__ a2, int n2) {
    if (g_mode != 1) return;
    int tid = blockIdx.x * blockDim.x + threadIdx.x;
    int stride = gridDim.x * blockDim.x;
#define FBA_BODY(ARR, N)                                                      \
    for (int i = tid; i < (N); i += stride) {                                 \
        uint4 v = __ldcs(&(ARR)[i]);                                          \
        atomicAdd(&g_histF[fmap_u(v.x) >> 16], 1u);                           \
        atomicAdd(&g_histF[fmap_u(v.y) >> 16], 1u);                           \
        atomicAdd(&g_histF[fmap_u(v.z) >> 16], 1u);                           \
        atomicAdd(&g_histF[fmap_u(v.w) >> 16], 1u);                           \
    }
    FBA_BODY(a0, n0)
    FBA_BODY(a1, n1)
    FBA_BODY(a2, n2)
#undef FBA_BODY
}

__global__ void k_fb_selectA() {
    if (g_mode != 1) return;
    unsigned bin, r;
    block_select64k(g_histF, g_rank, &bin, &r);
    if (threadIdx.x == 0) { g_prefix = bin; g_rank = r; }
}

// FALLBACK: full-read low-16-bit hist with prefix match.
__global__ void __launch_bounds__(NT) k_fb_histB(
        const uint4* __restrict__ a0, int n0,
        const uint4* __restrict__ a1, int n1,
        const uint4* __restrict__ a2, int n2) {
    if (g_mode != 1) return;
    const unsigned pref = g_prefix;
    int tid = blockIdx.x * blockDim.x + threadIdx.x;
    int stride = gridDim.x * blockDim.x;
#define FBB_BODY(ARR, N)                                                      \
    for (int i = tid; i < (N); i += stride) {                                 \
        uint4 v = __ldcs(&(ARR)[i]);                                          \
        unsigned k0 = fmap_u(v.x), k1 = fmap_u(v.y);                          \
        unsigned k2 = fmap_u(v.z), k3 = fmap_u(v.w);                          \
        if ((k0 >> 16) == pref) atomicAdd(&g_histB[k0 & 0xFFFFu], 1u);        \
        if ((k1 >> 16) == pref) atomicAdd(&g_histB[k1 & 0xFFFFu], 1u);        \
        if ((k2 >> 16) == pref) atomicAdd(&g_histB[k2 & 0xFFFFu], 1u);        \
        if ((k3 >> 16) == pref) atomicAdd(&g_histB[k3 & 0xFFFFu], 1u);        \
    }
    FBB_BODY(a0, n0)
    FBB_BODY(a1, n1)
    FBB_BODY(a2, n2)
#undef FBB_BODY
}

// ---------------------------------------------------------------------------
__global__ void k_selectB() {
    if (g_mode == 2) return;
    unsigned bin, r;
    block_select64k(g_histB, g_rank, &bin, &r);
    if (threadIdx.x == 0) {
        unsigned kf = (g_prefix << 16) | bin;
        g_key32 = kf;
        g_thresh = finv_map(kf);
    }
}

// ---------------------------------------------------------------------------
// Final: spec mode -> fixup only (zero candidates below thresh).
//        fallback/trivial -> full thresholded rewrite.
__global__ void __launch_bounds__(NT) k_final(
        const float4* __restrict__ a0, int n0,
        const float4* __restrict__ a1, int n1,
        const float4* __restrict__ a2, int n2,
        float4* __restrict__ out) {
    int mode = g_mode;
    if (mode == 0) {
        const unsigned kf = g_key32;
        unsigned lane = threadIdx.x & 31u;
        unsigned gw = (blockIdx.x * blockDim.x + threadIdx.x) >> 5;  // == slice
        unsigned cnt = g_warpcnt[gw];
        if (cnt > SLICE) cnt = SLICE;
        const uint2* sp = &g_pair[gw * SLICE];
        float* of = (float*)out;
        for (unsigned i = lane; i < cnt; i += 32) {
            uint2 p = sp[i];
            if (p.x < kf) of[p.y] = 0.0f;
        }
        return;
    }
    const float th = g_thresh;
    int tid = blockIdx.x * blockDim.x + threadIdx.x;
    int stride = gridDim.x * blockDim.x;
    for (int i = tid; i < n0; i += stride) {
        float4 v = a0[i];
        v.x = (v.x < th) ? 0.0f : v.x;  v.y = (v.y < th) ? 0.0f : v.y;
        v.z = (v.z < th) ? 0.0f : v.z;  v.w = (v.w < th) ? 0.0f : v.w;
        out[i] = v;
    }
    float4* o1 = out + n0;
    for (int i = tid; i < n1; i += stride) {
        float4 v = a1[i];
        v.x = (v.x < th) ? 0.0f : v.x;  v.y = (v.y < th) ? 0.0f : v.y;
        v.z = (v.z < th) ? 0.0f : v.z;  v.w = (v.w < th) ? 0.0f : v.w;
        o1[i] = v;
    }
    float4* o2 = out + n0 + n1;
    for (int i = tid; i < n2; i += stride) {
        float4 v = a2[i];
        v.x = (v.x < th) ? 0.0f : v.x;  v.y = (v.y < th) ? 0.0f : v.y;
        v.z = (v.z < th) ? 0.0f : v.z;  v.w = (v.w < th) ? 0.0f : v.w;
        o2[i] = v;
    }
}

// ============================================================================
extern "C" void kernel_launch(void* const* d_in, const int* in_sizes, int n_in,
                              void* d_out, int out_size) {
    const float* e  = (const float*)d_in[0];
    const float* m  = (const float*)d_in[1];
    const float* dp = (const float*)d_in[2];
    const int* mf_ptr = (n_in >= 4) ? (const int*)d_in[3] : nullptr;
    int ne = in_sizes[0], nm = in_sizes[1], nd = in_sizes[2];
    long long ntot = (long long)ne + (long long)nm + (long long)nd;
    int ne4 = ne / 4, nm4 = nm / 4, nd4 = nd / 4;

    const uint4* u0 = (const uint4*)e;
    const uint4* u1 = (const uint4*)m;
    const uint4* u2 = (const uint4*)dp;

    k_init<<<192, 1024>>>();
    k_pass1<<<NB, NT>>>(u0, ne4, u1, nm4, u2, nd4, (uint4*)d_out);
    k_selectA<<<1, 1024>>>(mf_ptr, 500000, ntot);
    k_histB<<<256, NT>>>();                                   // spec path
    k_fb_histA<<<148, NT>>>(u0, ne4, u1, nm4, u2, nd4);       // gated
    k_fb_selectA<<<1, 1024>>>();                              // gated
    k_fb_histB<<<148, NT>>>(u0, ne4, u1, nm4, u2, nd4);       // gated
    k_selectB<<<1, 1024>>>();
    k_final<<<NB, NT>>>((const float4*)e, ne4, (const float4*)m, nm4,
                        (const float4*)dp, nd4, (float4*)d_out);
}

// round 4
// speedup vs baseline: 4.1388x; 4.1388x over previous
#include <cuda_runtime.h>
#include <stdint.h>

// ============================================================================
// One-sweep speculative radix-select threshold kernel (v4).
//
// thresh = rank-mf (0-based) entry of the descending sort of all inputs.
// out[i] = x[i] < thresh ? 0 : x[i].
//
// Key map (order-preserving): key = u ^ (sign ? 0xFFFFFFFF : 0x80000000).
//
// pass1: read all, write out thresholded at 1.75, compact (key,idx) pairs of
// candidates (>=1.75) into per-warp slices, smem 256-bin hist of key>>24.
// Last block decides mode and selects digit 1.
// rounds 2..4: 256-bin smem hist over pairs (spec) or full data (fallback),
// select fused into last block of each round.
// final: spec -> zero candidates below exact key; fallback -> full rewrite.
// ============================================================================

#define NB    1024
#define NT    256
#define NWARP (NB * NT / 32)      // 8192
#define SLICE 512u
#define FKEY  0xBFE00000u         // key(+1.75f)
#define FBGRID 296
#define RGRID  256

__device__ unsigned g_h[256];
__device__ uint2    g_pair[NWARP * SLICE];   // 32 MB static scratch
__device__ unsigned g_warpcnt[NWARP];
__device__ unsigned g_ctr[8];
__device__ unsigned g_nscratch;
__device__ int      g_mode;       // 0=spec, 1=fallback, 2=trivial
__device__ int      g_overflow;
__device__ unsigned g_pref;       // accumulated digit prefix (right-aligned)
__device__ unsigned g_rank;       // residual rank
__device__ unsigned g_key32;      // final exact key
__device__ float    g_thresh;

__device__ __forceinline__ unsigned fmap_u(unsigned u) {
    return u ^ ((unsigned)((int)u >> 31) | 0x80000000u);
}
__device__ __forceinline__ float finv_map(unsigned k) {
    unsigned u = (k & 0x80000000u) ? (k ^ 0x80000000u) : ~k;
    return __uint_as_float(u);
}

// Block-cooperative digit select over g_h (call with all 256 threads).
// Loads hist, zeroes it for the next round, thread0 scans descending.
__device__ void select_digit(int append, int final_stage) {
    __shared__ unsigned sh[256];
    sh[threadIdx.x] = g_h[threadIdx.x];
    g_h[threadIdx.x] = 0;
    __syncthreads();
    if (threadIdx.x == 0) {
        unsigned r = g_rank;
        int b = 255;
        for (; b > 0; b--) { unsigned c = sh[b]; if (r < c) break; r -= c; }
        unsigned p = append ? ((g_pref << 8) | (unsigned)b) : (unsigned)b;
        g_pref = p;
        g_rank = r;
        if (final_stage) { g_key32 = p; g_thresh = finv_map(p); }
    }
    __syncthreads();
}

// ---------------------------------------------------------------------------
__global__ void k_init() {
    int i = threadIdx.x;
    g_h[i] = 0;
    if (i < 8) g_ctr[i] = 0;
    if (i == 0) {
        g_nscratch = 0; g_mode = 0; g_overflow = 0;
        g_pref = 0; g_rank = 0; g_key32 = 0; g_thresh = 0.0f;
    }
}

// ---------------------------------------------------------------------------
__global__ void __launch_bounds__(NT) k_pass1(
        const uint4* __restrict__ a0, int n0,
        const uint4* __restrict__ a1, int n1,
        const uint4* __restrict__ a2, int n2,
        uint4* __restrict__ out,
        const int* mf_ptr, int host_mf, long long ntot) {
    __shared__ unsigned shh[256];
    shh[threadIdx.x] = 0;
    __syncthreads();

    int tid = blockIdx.x * blockDim.x + threadIdx.x;
    int stride = gridDim.x * blockDim.x;
    unsigned lane = threadIdx.x & 31u;
    unsigned gw = (unsigned)tid >> 5;
    unsigned sbase = gw * SLICE;
    unsigned lt = (lane == 31u) ? 0x7FFFFFFFu : ((1u << lane) - 1u);
    unsigned me = 1u << lane;
    unsigned wo = 0;
    bool ovf = false;

#define P1_BODY(ARR, N, OUTP, EO)                                             \
    for (int i = tid; ; i += stride) {                                        \
        bool valid = i < (N);                                                 \
        if (!__any_sync(0xFFFFFFFFu, valid)) break;                           \
        uint4 v = valid ? __ldcs(&(ARR)[i]) : make_uint4(0u, 0u, 0u, 0u);     \
        unsigned k0 = fmap_u(v.x), k1 = fmap_u(v.y);                          \
        unsigned k2 = fmap_u(v.z), k3 = fmap_u(v.w);                          \
        bool c0 = valid && k0 >= FKEY, c1 = valid && k1 >= FKEY;              \
        bool c2 = valid && k2 >= FKEY, c3 = valid && k3 >= FKEY;              \
        if (valid) {                                                          \
            uint4 w;                                                          \
            w.x = c0 ? v.x : 0u;  w.y = c1 ? v.y : 0u;                        \
            w.z = c2 ? v.z : 0u;  w.w = c3 ? v.w : 0u;                        \
            __stcs(&(OUTP)[i], w);                                            \
        }                                                                     \
        unsigned b0 = __ballot_sync(0xFFFFFFFFu, c0);                         \
        unsigned b1 = __ballot_sync(0xFFFFFFFFu, c1);                         \
        unsigned b2 = __ballot_sync(0xFFFFFFFFu, c2);                         \
        unsigned b3 = __ballot_sync(0xFFFFFFFFu, c3);                         \
        unsigned t0 = __popc(b0), t1 = __popc(b1);                            \
        unsigned t2 = __popc(b2), t3 = __popc(b3);                            \
        unsigned tot = t0 + t1 + t2 + t3;                                     \
        if (tot) {                                                            \
            if (wo + tot <= SLICE) {                                          \
                unsigned o = sbase + wo;                                      \
                unsigned ib = (EO) + 4u * (unsigned)i;                        \
                if (c0) { g_pair[o + __popc(b0 & lt)] = make_uint2(k0, ib);   \
                          atomicAdd(&shh[k0 >> 24], 1u); }                    \
                o += t0;                                                      \
                if (c1) { g_pair[o + __popc(b1 & lt)] = make_uint2(k1, ib+1); \
                          atomicAdd(&shh[k1 >> 24], 1u); }                    \
                o += t1;                                                      \
                if (c2) { g_pair[o + __popc(b2 & lt)] = make_uint2(k2, ib+2); \
                          atomicAdd(&shh[k2 >> 24], 1u); }                    \
                o += t2;                                                      \
                if (c3) { g_pair[o + __popc(b3 & lt)] = make_uint2(k3, ib+3); \
                          atomicAdd(&shh[k3 >> 24], 1u); }                    \
                wo += tot;                                                    \
            } else {                                                          \
                ovf = true;                                                   \
            }                                                                 \
        }                                                                     \
    }
    P1_BODY(a0, n0, out, 0u)
    P1_BODY(a1, n1, out + n0, 4u * (unsigned)n0)
    P1_BODY(a2, n2, out + n0 + n1, 4u * (unsigned)(n0 + n1))
#undef P1_BODY

    if (ovf) g_overflow = 1;
    if (lane == 0) {
        g_warpcnt[gw] = wo;
        atomicAdd(&g_nscratch, wo);
    }
    __syncthreads();
    if (shh[threadIdx.x]) atomicAdd(&g_h[threadIdx.x], shh[threadIdx.x]);
    __threadfence();

    __shared__ unsigned islast;
    if (threadIdx.x == 0)
        islast = (atomicAdd(&g_ctr[0], 1u) == gridDim.x - 1u) ? 1u : 0u;
    __syncthreads();
    if (!islast) return;

    // Last block: decide mode, select digit 1 (spec path).
    __shared__ int smode;
    if (threadIdx.x == 0) {
        long long mf = (mf_ptr != nullptr) ? (long long)(*mf_ptr)
                                           : (long long)host_mf;
        if (mf < 0) mf = 0;
        int mode;
        if (mf >= ntot)                                        mode = 2;
        else if (g_overflow || (long long)g_nscratch < mf + 1) mode = 1;
        else                                                   mode = 0;
        g_mode = mode;
        smode = mode;
        g_rank = (unsigned)mf;
        if (mode == 2) g_thresh = 0.0f;
    }
    __syncthreads();
    if (smode == 0) select_digit(0, 0);
}

// ---------------------------------------------------------------------------
// FALLBACK digit 1: full-read 256-bin hist of key>>24 (gated; mode 1 only).
__global__ void __launch_bounds__(NT) k_fb1(
        const uint4* __restrict__ a0, int n0,
        const uint4* __restrict__ a1, int n1,
        const uint4* __restrict__ a2, int n2) {
    int mode = g_mode;
    __shared__ unsigned shh[256];
    shh[threadIdx.x] = 0;
    __syncthreads();
    if (mode == 1) {
        int tid = blockIdx.x * blockDim.x + threadIdx.x;
        int stride = gridDim.x * blockDim.x;
#define FB1_BODY(ARR, N)                                                      \
        for (int i = tid; i < (N); i += stride) {                             \
            uint4 v = __ldcs(&(ARR)[i]);                                      \
            atomicAdd(&shh[fmap_u(v.x) >> 24], 1u);                           \
            atomicAdd(&shh[fmap_u(v.y) >> 24], 1u);                           \
            atomicAdd(&shh[fmap_u(v.z) >> 24], 1u);                           \
            atomicAdd(&shh[fmap_u(v.w) >> 24], 1u);                           \
        }
        FB1_BODY(a0, n0)
        FB1_BODY(a1, n1)
        FB1_BODY(a2, n2)
#undef FB1_BODY
    }
    __syncthreads();
    if (shh[threadIdx.x]) atomicAdd(&g_h[threadIdx.x], shh[threadIdx.x]);
    __threadfence();
    __shared__ unsigned islast;
    if (threadIdx.x == 0)
        islast = (atomicAdd(&g_ctr[1], 1u) == gridDim.x - 1u) ? 1u : 0u;
    __syncthreads();
    if (islast && mode == 1) select_digit(0, 0);
}

// ---------------------------------------------------------------------------
// Rounds 2..4: smem hist of digit R; spec reads pairs, fallback re-reads input.
template <int R>
__global__ void __launch_bounds__(NT) k_round(
        const uint4* __restrict__ a0, int n0,
        const uint4* __restrict__ a1, int n1,
        const uint4* __restrict__ a2, int n2) {
    int mode = g_mode;
    __shared__ unsigned shh[256];
    shh[threadIdx.x] = 0;
    __syncthreads();
    const unsigned pref = g_pref;
    constexpr int SD = 32 - 8 * R;

    if (mode == 0) {
        unsigned lane = threadIdx.x & 31u;
        unsigned w = (blockIdx.x * blockDim.x + threadIdx.x) >> 5;
        unsigned nwg = (gridDim.x * blockDim.x) >> 5;
        for (unsigned s = w; s < NWARP; s += nwg) {
            unsigned cnt = g_warpcnt[s];
            if (cnt > SLICE) cnt = SLICE;
            const uint2* sp = &g_pair[s * SLICE];
            for (unsigned i = lane; i < cnt; i += 32) {
                unsigned k = sp[i].x;
                if ((k >> (SD + 8)) == pref)
                    atomicAdd(&shh[(k >> SD) & 255u], 1u);
            }
        }
    } else if (mode == 1) {
        int tid = blockIdx.x * blockDim.x + threadIdx.x;
        int stride = gridDim.x * blockDim.x;
#define RD_BODY(ARR, N)                                                       \
        for (int i = tid; i < (N); i += stride) {                             \
            uint4 v = __ldcs(&(ARR)[i]);                                      \
            unsigned k0 = fmap_u(v.x), k1 = fmap_u(v.y);                      \
            unsigned k2 = fmap_u(v.z), k3 = fmap_u(v.w);                      \
            if ((k0 >> (SD + 8)) == pref) atomicAdd(&shh[(k0 >> SD) & 255u], 1u); \
            if ((k1 >> (SD + 8)) == pref) atomicAdd(&shh[(k1 >> SD) & 255u], 1u); \
            if ((k2 >> (SD + 8)) == pref) atomicAdd(&shh[(k2 >> SD) & 255u], 1u); \
            if ((k3 >> (SD + 8)) == pref) atomicAdd(&shh[(k3 >> SD) & 255u], 1u); \
        }
        RD_BODY(a0, n0)
        RD_BODY(a1, n1)
        RD_BODY(a2, n2)
#undef RD_BODY
    }
    __syncthreads();
    if (shh[threadIdx.x]) atomicAdd(&g_h[threadIdx.x], shh[threadIdx.x]);
    __threadfence();
    __shared__ unsigned islast;
    if (threadIdx.x == 0)
        islast = (atomicAdd(&g_ctr[R], 1u) == gridDim.x - 1u) ? 1u : 0u;
    __syncthreads();
    if (islast && mode != 2) select_digit(1, R == 4);
}

// ---------------------------------------------------------------------------
// Final: spec -> scattered fixup; fallback/trivial -> full rewrite.
__global__ void __launch_bounds__(NT) k_final(
        const float4* __restrict__ a0, int n0,
        const float4* __restrict__ a1, int n1,
        const float4* __restrict__ a2, int n2,
        float4* __restrict__ out) {
    int mode = g_mode;
    if (mode == 0) {
        const unsigned kf = g_key32;
        unsigned lane = threadIdx.x & 31u;
        unsigned gw = (blockIdx.x * blockDim.x + threadIdx.x) >> 5;  // slice id
        unsigned cnt = g_warpcnt[gw];
        if (cnt > SLICE) cnt = SLICE;
        const uint2* sp = &g_pair[gw * SLICE];
        float* of = (float*)out;
        for (unsigned i = lane; i < cnt; i += 32) {
            uint2 p = sp[i];
            if (p.x < kf) of[p.y] = 0.0f;
        }
        return;
    }
    const float th = g_thresh;
    int tid = blockIdx.x * blockDim.x + threadIdx.x;
    int stride = gridDim.x * blockDim.x;
    for (int i = tid; i < n0; i += stride) {
        float4 v = a0[i];
        v.x = (v.x < th) ? 0.0f : v.x;  v.y = (v.y < th) ? 0.0f : v.y;
        v.z = (v.z < th) ? 0.0f : v.z;  v.w = (v.w < th) ? 0.0f : v.w;
        out[i] = v;
    }
    float4* o1 = out + n0;
    for (int i = tid; i < n1; i += stride) {
        float4 v = a1[i];
        v.x = (v.x < th) ? 0.0f : v.x;  v.y = (v.y < th) ? 0.0f : v.y;
        v.z = (v.z < th) ? 0.0f : v.z;  v.w = (v.w < th) ? 0.0f : v.w;
        o1[i] = v;
    }
    float4* o2 = out + n0 + n1;
    for (int i = tid; i < n2; i += stride) {
        float4 v = a2[i];
        v.x = (v.x < th) ? 0.0f : v.x;  v.y = (v.y < th) ? 0.0f : v.y;
        v.z = (v.z < th) ? 0.0f : v.z;  v.w = (v.w < th) ? 0.0f : v.w;
        o2[i] = v;
    }
}

// ============================================================================
extern "C" void kernel_launch(void* const* d_in, const int* in_sizes, int n_in,
                              void* d_out, int out_size) {
    const float* e  = (const float*)d_in[0];
    const float* m  = (const float*)d_in[1];
    const float* dp = (const float*)d_in[2];
    const int* mf_ptr = (n_in >= 4) ? (const int*)d_in[3] : nullptr;
    int ne = in_sizes[0], nm = in_sizes[1], nd = in_sizes[2];
    long long ntot = (long long)ne + (long long)nm + (long long)nd;
    int ne4 = ne / 4, nm4 = nm / 4, nd4 = nd / 4;

    const uint4* u0 = (const uint4*)e;
    const uint4* u1 = (const uint4*)m;
    const uint4* u2 = (const uint4*)dp;

    k_init<<<1, 256>>>();
    k_pass1<<<NB, NT>>>(u0, ne4, u1, nm4, u2, nd4, (uint4*)d_out,
                        mf_ptr, 500000, ntot);
    k_fb1<<<FBGRID, NT>>>(u0, ne4, u1, nm4, u2, nd4);
    k_round<2><<<RGRID, NT>>>(u0, ne4, u1, nm4, u2, nd4);
    k_round<3><<<RGRID, NT>>>(u0, ne4, u1, nm4, u2, nd4);
    k_round<4><<<RGRID, NT>>>(u0, ne4, u1, nm4, u2, nd4);
    k_final<<<NB, NT>>>((const float4*)e, ne4, (const float4*)m, nm4,
                        (const float4*)dp, nd4, (float4*)d_out);
}

// round 5
// speedup vs baseline: 5.0329x; 1.2160x over previous
#include <cuda_runtime.h>
#include <stdint.h>

// ============================================================================
// One-sweep speculative radix-select threshold kernel (v5).
//
// thresh = rank-mf (0-based) entry of the descending sort of all inputs.
// out[i] = x[i] < thresh ? 0 : x[i].
//
// Key map (order-preserving): key = u ^ (sign ? 0xFFFFFFFF : 0x80000000).
//
// pass1: read all, write out thresholded at 1.75, compact key/idx (SoA) of
// candidates (>=1.75) into per-warp slices, smem 4096-bin hist of key>>20.
// Last block decides mode and selects digit 1 (12 bits).
// round A: 4096-bin hist of bits[19:8] over keys (spec) or full data (fb).
// round B: 256-bin hist of bits[7:0]. Selects fused in last blocks.
// final: spec -> zero candidates below exact key; fallback -> full rewrite.
// ============================================================================

#define NB     1024
#define NT     256
#define NWARP  (NB * NT / 32)     // 8192
#define SLICE  512u
#define FKEY   0xBFE00000u        // key(+1.75f)
#define HBINS  4096

__device__ unsigned g_h[HBINS];
__device__ unsigned g_key[NWARP * SLICE];   // 16 MB
__device__ unsigned g_idx[NWARP * SLICE];   // 16 MB
__device__ unsigned g_warpcnt[NWARP];
__device__ unsigned g_ctr[8];
__device__ unsigned g_nscratch;
__device__ int      g_mode;       // 0=spec, 1=fallback, 2=trivial
__device__ int      g_overflow;
__device__ unsigned g_pref;       // accumulated digit prefix (right-aligned)
__device__ unsigned g_rank;       // residual rank
__device__ unsigned g_key32;      // final exact key
__device__ float    g_thresh;

__device__ __forceinline__ unsigned fmap_u(unsigned u) {
    return u ^ ((unsigned)((int)u >> 31) | 0x80000000u);
}
__device__ __forceinline__ float finv_map(unsigned k) {
    unsigned u = (k & 0x80000000u) ? (k ^ 0x80000000u) : ~k;
    return __uint_as_float(u);
}

// Block-cooperative descending rank-select over g_h[0..nbins). 256 threads.
// Appends the selected digit to g_pref, updates g_rank, zeroes g_h.
__device__ void select_digitN(int nbins, int append_bits, int final_stage) {
    __shared__ unsigned tsum[256];
    __shared__ unsigned wsum[8];
    int per = nbins >> 8;
    unsigned s = 0;
    int base = threadIdx.x * per;
    for (int j = 0; j < per; j++) s += g_h[base + j];
    tsum[threadIdx.x] = s;
    unsigned ws = s;
    ws += __shfl_xor_sync(0xFFFFFFFFu, ws, 16);
    ws += __shfl_xor_sync(0xFFFFFFFFu, ws, 8);
    ws += __shfl_xor_sync(0xFFFFFFFFu, ws, 4);
    ws += __shfl_xor_sync(0xFFFFFFFFu, ws, 2);
    ws += __shfl_xor_sync(0xFFFFFFFFu, ws, 1);
    if ((threadIdx.x & 31) == 0) wsum[threadIdx.x >> 5] = ws;
    __syncthreads();
    if (threadIdx.x == 0) {
        unsigned r = g_rank;
        int w = 7;
        for (; w > 0; w--) { if (r < wsum[w]) break; r -= wsum[w]; }
        int t = 31;
        for (; t > 0; t--) { unsigned c = tsum[w * 32 + t]; if (r < c) break; r -= c; }
        int b = (w * 32 + t) * per;
        int j = per - 1;
        for (; j > 0; j--) { unsigned c = g_h[b + j]; if (r < c) break; r -= c; }
        unsigned d = (unsigned)(b + j);
        unsigned p = (g_pref << append_bits) | d;
        g_pref = p;
        g_rank = r;
        if (final_stage) { g_key32 = p; g_thresh = finv_map(p); }
    }
    __syncthreads();
    for (int j = threadIdx.x; j < nbins; j += 256) g_h[j] = 0;
    __syncthreads();
}

// ---------------------------------------------------------------------------
__global__ void k_init() {
    int i = blockIdx.x * blockDim.x + threadIdx.x;
    if (i < HBINS) g_h[i] = 0;
    if (i < 8) g_ctr[i] = 0;
    if (i == 0) {
        g_nscratch = 0; g_mode = 0; g_overflow = 0;
        g_pref = 0; g_rank = 0; g_key32 = 0; g_thresh = 0.0f;
    }
}

// ---------------------------------------------------------------------------
__global__ void __launch_bounds__(NT) k_pass1(
        const uint4* __restrict__ a0, int n0,
        const uint4* __restrict__ a1, int n1,
        const uint4* __restrict__ a2, int n2,
        uint4* __restrict__ out,
        const int* mf_ptr, int host_mf, long long ntot) {
    __shared__ unsigned shh[HBINS];
    for (int j = threadIdx.x; j < HBINS; j += NT) shh[j] = 0;
    __syncthreads();

    int tid = blockIdx.x * blockDim.x + threadIdx.x;
    int stride = gridDim.x * blockDim.x;
    unsigned lane = threadIdx.x & 31u;
    unsigned gw = (unsigned)tid >> 5;
    unsigned sbase = gw * SLICE;
    unsigned lt = (lane == 31u) ? 0x7FFFFFFFu : ((1u << lane) - 1u);
    unsigned me = 1u << lane;
    unsigned wo = 0;
    bool ovf = false;

#define P1_BODY(ARR, N, OUTP, EO)                                             \
    for (int i = tid; ; i += stride) {                                        \
        bool valid = i < (N);                                                 \
        if (!__any_sync(0xFFFFFFFFu, valid)) break;                           \
        uint4 v = valid ? __ldcs(&(ARR)[i]) : make_uint4(0u, 0u, 0u, 0u);     \
        unsigned k0 = fmap_u(v.x), k1 = fmap_u(v.y);                          \
        unsigned k2 = fmap_u(v.z), k3 = fmap_u(v.w);                          \
        bool c0 = valid && k0 >= FKEY, c1 = valid && k1 >= FKEY;              \
        bool c2 = valid && k2 >= FKEY, c3 = valid && k3 >= FKEY;              \
        if (valid) {                                                          \
            uint4 w;                                                          \
            w.x = c0 ? v.x : 0u;  w.y = c1 ? v.y : 0u;                        \
            w.z = c2 ? v.z : 0u;  w.w = c3 ? v.w : 0u;                        \
            __stcs(&(OUTP)[i], w);                                            \
        }                                                                     \
        unsigned b0 = __ballot_sync(0xFFFFFFFFu, c0);                         \
        unsigned b1 = __ballot_sync(0xFFFFFFFFu, c1);                         \
        unsigned b2 = __ballot_sync(0xFFFFFFFFu, c2);                         \
        unsigned b3 = __ballot_sync(0xFFFFFFFFu, c3);                         \
        unsigned t0 = __popc(b0), t1 = __popc(b1);                            \
        unsigned t2 = __popc(b2), t3 = __popc(b3);                            \
        unsigned tot = t0 + t1 + t2 + t3;                                     \
        if (tot) {                                                            \
            if (wo + tot <= SLICE) {                                          \
                unsigned o = sbase + wo;                                      \
                unsigned ib = (EO) + 4u * (unsigned)i;                        \
                unsigned p;                                                   \
                if (c0) { p = o + __popc(b0 & lt);                            \
                          g_key[p] = k0; g_idx[p] = ib;                       \
                          atomicAdd(&shh[k0 >> 20], 1u); }                    \
                o += t0;                                                      \
                if (c1) { p = o + __popc(b1 & lt);                            \
                          g_key[p] = k1; g_idx[p] = ib + 1u;                  \
                          atomicAdd(&shh[k1 >> 20], 1u); }                    \
                o += t1;                                                      \
                if (c2) { p = o + __popc(b2 & lt);                            \
                          g_key[p] = k2; g_idx[p] = ib + 2u;                  \
                          atomicAdd(&shh[k2 >> 20], 1u); }                    \
                o += t2;                                                      \
                if (c3) { p = o + __popc(b3 & lt);                            \
                          g_key[p] = k3; g_idx[p] = ib + 3u;                  \
                          atomicAdd(&shh[k3 >> 20], 1u); }                    \
                wo += tot;                                                    \
            } else {                                                          \
                ovf = true;                                                   \
            }                                                                 \
        }                                                                     \
    }
    P1_BODY(a0, n0, out, 0u)
    P1_BODY(a1, n1, out + n0, 4u * (unsigned)n0)
    P1_BODY(a2, n2, out + n0 + n1, 4u * (unsigned)(n0 + n1))
#undef P1_BODY

    if (ovf) g_overflow = 1;
    if (lane == 0) {
        g_warpcnt[gw] = wo;
        atomicAdd(&g_nscratch, wo);
    }
    __syncthreads();
    for (int j = threadIdx.x; j < HBINS; j += NT)
        if (shh[j]) atomicAdd(&g_h[j], shh[j]);
    __threadfence();

    __shared__ unsigned islast;
    if (threadIdx.x == 0)
        islast = (atomicAdd(&g_ctr[0], 1u) == gridDim.x - 1u) ? 1u : 0u;
    __syncthreads();
    if (!islast) return;

    __shared__ int smode;
    if (threadIdx.x == 0) {
        long long mf = (mf_ptr != nullptr) ? (long long)(*mf_ptr)
                                           : (long long)host_mf;
        if (mf < 0) mf = 0;
        int mode;
        if (mf >= ntot)                                        mode = 2;
        else if (g_overflow || (long long)g_nscratch < mf + 1) mode = 1;
        else                                                   mode = 0;
        g_mode = mode;
        smode = mode;
        g_rank = (unsigned)mf;
        if (mode == 2) g_thresh = 0.0f;
    }
    __syncthreads();
    if (smode == 0) select_digitN(HBINS, 12, 0);
}

// ---------------------------------------------------------------------------
// FALLBACK digit 1: full-read 4096-bin hist of key>>20 (gated; mode 1 only).
__global__ void __launch_bounds__(NT) k_fb1(
        const uint4* __restrict__ a0, int n0,
        const uint4* __restrict__ a1, int n1,
        const uint4* __restrict__ a2, int n2) {
    int mode = g_mode;
    __shared__ unsigned shh[HBINS];
    if (mode == 1) {
        for (int j = threadIdx.x; j < HBINS; j += NT) shh[j] = 0;
        __syncthreads();
        int tid = blockIdx.x * blockDim.x + threadIdx.x;
        int stride = gridDim.x * blockDim.x;
#define FB1_BODY(ARR, N)                                                      \
        for (int i = tid; i < (N); i += stride) {                             \
            uint4 v = __ldcs(&(ARR)[i]);                                      \
            atomicAdd(&shh[fmap_u(v.x) >> 20], 1u);                           \
            atomicAdd(&shh[fmap_u(v.y) >> 20], 1u);                           \
            atomicAdd(&shh[fmap_u(v.z) >> 20], 1u);                           \
            atomicAdd(&shh[fmap_u(v.w) >> 20], 1u);                           \
        }
        FB1_BODY(a0, n0)
        FB1_BODY(a1, n1)
        FB1_BODY(a2, n2)
#undef FB1_BODY
        __syncthreads();
        for (int j = threadIdx.x; j < HBINS; j += NT)
            if (shh[j]) atomicAdd(&g_h[j], shh[j]);
        __threadfence();
    }
    __shared__ unsigned islast;
    if (threadIdx.x == 0)
        islast = (atomicAdd(&g_ctr[1], 1u) == gridDim.x - 1u) ? 1u : 0u;
    __syncthreads();
    if (islast && mode == 1) select_digitN(HBINS, 12, 0);
}

// ---------------------------------------------------------------------------
// Rounds: digit = (key >> SD) & ((1<<DB)-1), prefix = key >> (SD+DB).
// Round A: SD=8, DB=12 (ctr 2). Round B: SD=0, DB=8 (ctr 3, final).
template <int SD, int DB, int CTR, int FINAL>
__global__ void __launch_bounds__(NT) k_round(
        const uint4* __restrict__ a0, int n0,
        const uint4* __restrict__ a1, int n1,
        const uint4* __restrict__ a2, int n2) {
    int mode = g_mode;
    constexpr int NBINS = 1 << DB;
    constexpr unsigned DMASK = (1u << DB) - 1u;
    __shared__ unsigned shh[NBINS];
    for (int j = threadIdx.x; j < NBINS; j += NT) shh[j] = 0;
    __syncthreads();
    const unsigned pref = g_pref;

    if (mode == 0) {
        unsigned lane = threadIdx.x & 31u;
        unsigned s = (blockIdx.x * blockDim.x + threadIdx.x) >> 5;  // slice id
        unsigned cnt = g_warpcnt[s];
        if (cnt > SLICE) cnt = SLICE;
        const unsigned* kp = &g_key[s * SLICE];
        for (unsigned i = lane; i < cnt; i += 32) {
            unsigned k = kp[i];
            if ((k >> (SD + DB)) == pref)
                atomicAdd(&shh[(k >> SD) & DMASK], 1u);
        }
    } else if (mode == 1) {
        int tid = blockIdx.x * blockDim.x + threadIdx.x;
        int stride = gridDim.x * blockDim.x;
#define RD_BODY(ARR, N)                                                       \
        for (int i = tid; i < (N); i += stride) {                             \
            uint4 v = __ldcs(&(ARR)[i]);                                      \
            unsigned k0 = fmap_u(v.x), k1 = fmap_u(v.y);                      \
            unsigned k2 = fmap_u(v.z), k3 = fmap_u(v.w);                      \
            if ((k0 >> (SD + DB)) == pref) atomicAdd(&shh[(k0 >> SD) & DMASK], 1u); \
            if ((k1 >> (SD + DB)) == pref) atomicAdd(&shh[(k1 >> SD) & DMASK], 1u); \
            if ((k2 >> (SD + DB)) == pref) atomicAdd(&shh[(k2 >> SD) & DMASK], 1u); \
            if ((k3 >> (SD + DB)) == pref) atomicAdd(&shh[(k3 >> SD) & DMASK], 1u); \
        }
        RD_BODY(a0, n0)
        RD_BODY(a1, n1)
        RD_BODY(a2, n2)
#undef RD_BODY
    }
    __syncthreads();
    for (int j = threadIdx.x; j < NBINS; j += NT)
        if (shh[j]) atomicAdd(&g_h[j], shh[j]);
    __threadfence();
    __shared__ unsigned islast;
    if (threadIdx.x == 0)
        islast = (atomicAdd(&g_ctr[CTR], 1u) == gridDim.x - 1u) ? 1u : 0u;
    __syncthreads();
    if (islast && mode != 2) select_digitN(NBINS, DB, FINAL);
}

// ---------------------------------------------------------------------------
// Final: spec -> scattered fixup; fallback/trivial -> full rewrite.
__global__ void __launch_bounds__(NT) k_final(
        const float4* __restrict__ a0, int n0,
        const float4* __restrict__ a1, int n1,
        const float4* __restrict__ a2, int n2,
        float4* __restrict__ out) {
    int mode = g_mode;
    if (mode == 0) {
        const unsigned kf = g_key32;
        unsigned lane = threadIdx.x & 31u;
        unsigned s = (blockIdx.x * blockDim.x + threadIdx.x) >> 5;  // slice id
        unsigned cnt = g_warpcnt[s];
        if (cnt > SLICE) cnt = SLICE;
        const unsigned* kp = &g_key[s * SLICE];
        const unsigned* ip = &g_idx[s * SLICE];
        float* of = (float*)out;
        for (unsigned i = lane; i < cnt; i += 32) {
            unsigned k = kp[i];
            if (k < kf) of[ip[i]] = 0.0f;
        }
        return;
    }
    const float th = g_thresh;
    int tid = blockIdx.x * blockDim.x + threadIdx.x;
    int stride = gridDim.x * blockDim.x;
    for (int i = tid; i < n0; i += stride) {
        float4 v = a0[i];
        v.x = (v.x < th) ? 0.0f : v.x;  v.y = (v.y < th) ? 0.0f : v.y;
        v.z = (v.z < th) ? 0.0f : v.z;  v.w = (v.w < th) ? 0.0f : v.w;
        out[i] = v;
    }
    float4* o1 = out + n0;
    for (int i = tid; i < n1; i += stride) {
        float4 v = a1[i];
        v.x = (v.x < th) ? 0.0f : v.x;  v.y = (v.y < th) ? 0.0f : v.y;
        v.z = (v.z < th) ? 0.0f : v.z;  v.w = (v.w < th) ? 0.0f : v.w;
        o1[i] = v;
    }
    float4* o2 = out + n0 + n1;
    for (int i = tid; i < n2; i += stride) {
        float4 v = a2[i];
        v.x = (v.x < th) ? 0.0f : v.x;  v.y = (v.y < th) ? 0.0f : v.y;
        v.z = (v.z < th) ? 0.0f : v.z;  v.w = (v.w < th) ? 0.0f : v.w;
        o2[i] = v;
    }
}

// ============================================================================
extern "C" void kernel_launch(void* const* d_in, const int* in_sizes, int n_in,
                              void* d_out, int out_size) {
    const float* e  = (const float*)d_in[0];
    const float* m  = (const float*)d_in[1];
    const float* dp = (const float*)d_in[2];
    const int* mf_ptr = (n_in >= 4) ? (const int*)d_in[3] : nullptr;
    int ne = in_sizes[0], nm = in_sizes[1], nd = in_sizes[2];
    long long ntot = (long long)ne + (long long)nm + (long long)nd;
    int ne4 = ne / 4, nm4 = nm / 4, nd4 = nd / 4;

    const uint4* u0 = (const uint4*)e;
    const uint4* u1 = (const uint4*)m;
    const uint4* u2 = (const uint4*)dp;

    k_init<<<16, 256>>>();
    k_pass1<<<NB, NT>>>(u0, ne4, u1, nm4, u2, nd4, (uint4*)d_out,
                        mf_ptr, 500000, ntot);
    k_fb1<<<296, NT>>>(u0, ne4, u1, nm4, u2, nd4);
    k_round<8, 12, 2, 0><<<NB, NT>>>(u0, ne4, u1, nm4, u2, nd4);
    k_round<0, 8, 3, 1><<<NB, NT>>>(u0, ne4, u1, nm4, u2, nd4);
    k_final<<<NB, NT>>>((const float4*)e, ne4, (const float4*)m, nm4,
                        (const float4*)dp, nd4, (float4*)d_out);
}